// round 2
// baseline (speedup 1.0000x reference)
#include <cuda_runtime.h>
#include <cstdint>
#include <math.h>

#define STEPS 511
#define BATCH 8
#define HID   256
#define G4    1024
#define VOCAB 32000
#define NROWS (STEPS*BATCH)   // 4088

// ---------------- scratch (no allocs allowed) ----------------
__device__ float g_xp[STEPS*BATCH*G4];    // 16.7 MB
__device__ float g_h1[STEPS*BATCH*HID];   // 4.2 MB
__device__ float g_h2[STEPS*BATCH*HID];   // 4.2 MB
__device__ float g_gate[NROWS];

__device__ __forceinline__ float sigmoidf_(float x){ return 1.0f/(1.0f + __expf(-x)); }

// ============================================================
// Input projection: g_xp[r][c] = dot(A_row(r), W[c]) + b1[c]+b2[c]
// A_row: emb_w[captions[b][t]] (K=128) for layer 0, g_h1 row (K=256) for layer 1
// ============================================================
__global__ void __launch_bounds__(256) xp_kernel(
    const int* __restrict__ captions,     // nullable
    const float* __restrict__ emb_w,      // nullable
    const float* __restrict__ W,          // (1024, K)
    const float* __restrict__ bias1,
    const float* __restrict__ bias2,
    int K)
{
  __shared__ __align__(16) float As[8][256];
  const int tid = threadIdx.x;
  const int r0  = blockIdx.x * 8;

  for (int idx = tid; idx < 8*K; idx += 256) {
    int row = idx / K, k = idx - row*K;
    int r = r0 + row;
    const float* src;
    if (captions) { int b = r & 7; int t = r >> 3; src = emb_w + (size_t)captions[b*512 + t] * K; }
    else          { src = g_h1 + (size_t)r * K; }
    As[row][k] = src[k];
  }
  __syncthreads();

  float acc[4][8];
  #pragma unroll
  for (int i=0;i<4;i++)
    #pragma unroll
    for (int r=0;r<8;r++) acc[i][r]=0.f;

  const int c0 = tid;
  for (int k0 = 0; k0 < K; k0 += 4) {
    float4 w0 = *(const float4*)&W[(size_t)(c0      )*K + k0];
    float4 w1 = *(const float4*)&W[(size_t)(c0+256)*K + k0];
    float4 w2 = *(const float4*)&W[(size_t)(c0+512)*K + k0];
    float4 w3 = *(const float4*)&W[(size_t)(c0+768)*K + k0];
    const float* v0 = (const float*)&w0;
    const float* v1 = (const float*)&w1;
    const float* v2 = (const float*)&w2;
    const float* v3 = (const float*)&w3;
    #pragma unroll
    for (int kk=0; kk<4; kk++) {
      #pragma unroll
      for (int r=0;r<8;r++) {
        float a = As[r][k0+kk];
        acc[0][r] = fmaf(v0[kk], a, acc[0][r]);
        acc[1][r] = fmaf(v1[kk], a, acc[1][r]);
        acc[2][r] = fmaf(v2[kk], a, acc[2][r]);
        acc[3][r] = fmaf(v3[kk], a, acc[3][r]);
      }
    }
  }
  #pragma unroll
  for (int i=0;i<4;i++) {
    int c = c0 + i*256;
    float bb = bias1[c] + bias2[c];
    #pragma unroll
    for (int r=0;r<8;r++)
      g_xp[(size_t)(r0+r)*G4 + c] = acc[i][r] + bb;
  }
}

// ============================================================
// LSTM scan: 8 clusters (one per batch) x 8 CTAs x 256 threads.
// CTA j owns hidden units [32j, 32j+32) => 128 gate-rows, weights in registers.
// h exchanged between the 8 CTAs via DSMEM each step, cluster.sync barrier.
// ============================================================
__device__ __forceinline__ void st_remote_f32(uint32_t saddr, uint32_t rank, float v) {
  asm volatile("{\n\t.reg .b32 ra;\n\t"
               "mapa.shared::cluster.u32 ra, %0, %1;\n\t"
               "st.shared::cluster.f32 [ra], %2;\n\t}"
               :: "r"(saddr), "r"(rank), "f"(v) : "memory");
}
__device__ __forceinline__ void cluster_sync_() {
  asm volatile("barrier.cluster.arrive.aligned;" ::: "memory");
  asm volatile("barrier.cluster.wait.aligned;"   ::: "memory");
}

__global__ __launch_bounds__(256,1) __cluster_dims__(8,1,1)
void lstm_scan(const float* __restrict__ w_hh,
               const float* __restrict__ thought,
               int layer)
{
  __shared__ __align__(16) float h_s[2][HID];
  __shared__ __align__(16) float gates_s[128];
  __shared__ float c_s[32];

  float* __restrict__ h_out = layer ? g_h2 : g_h1;

  const int tid = threadIdx.x;
  const int b   = blockIdx.x >> 3;   // batch = cluster id
  const int j   = blockIdx.x & 7;    // rank within cluster
  const int rq  = tid >> 3;          // 0..31 : row quad
  const int kp  = tid & 7;           // 0..7  : k partition (32 k each)
  const int gidx = rq >> 3;          // gate (i,f,g,o)
  const int ulb  = (4*rq) & 31;      // unit base within slice
  const int Gbase = gidx*256 + 32*j + ulb;  // global gate row base (4 consecutive)

  // register-resident W_hh slice: 4 rows x 32 k = 128 floats
  float wreg[4][32];
  #pragma unroll
  for (int i=0;i<4;i++){
    const float* wp = w_hh + (size_t)(Gbase+i)*HID + 32*kp;
    #pragma unroll
    for (int q=0;q<8;q++){
      float4 v = *(const float4*)(wp + 4*q);
      wreg[i][4*q+0]=v.x; wreg[i][4*q+1]=v.y; wreg[i][4*q+2]=v.z; wreg[i][4*q+3]=v.w;
    }
  }
  h_s[0][tid] = thought[b*HID + tid];
  if (tid < 32) c_s[tid] = 0.f;
  __syncthreads();
  cluster_sync_();

  uint32_t hs0 = (uint32_t)__cvta_generic_to_shared(&h_s[0][0]);
  uint32_t hs1 = (uint32_t)__cvta_generic_to_shared(&h_s[1][0]);

  for (int t = 0; t < STEPS; t++) {
    const int cur = t & 1;
    float4 xpv = make_float4(0.f,0.f,0.f,0.f);
    if (kp == 0)
      xpv = *(const float4*)&g_xp[(size_t)(t*BATCH + b)*G4 + Gbase];

    float a0=0.f,a1=0.f,a2=0.f,a3=0.f;
    const float4* h4 = (const float4*)&h_s[cur][32*kp];
    #pragma unroll
    for (int q=0;q<8;q++) {
      float4 hv = h4[q];
      a0=fmaf(wreg[0][4*q+0],hv.x,a0); a0=fmaf(wreg[0][4*q+1],hv.y,a0);
      a0=fmaf(wreg[0][4*q+2],hv.z,a0); a0=fmaf(wreg[0][4*q+3],hv.w,a0);
      a1=fmaf(wreg[1][4*q+0],hv.x,a1); a1=fmaf(wreg[1][4*q+1],hv.y,a1);
      a1=fmaf(wreg[1][4*q+2],hv.z,a1); a1=fmaf(wreg[1][4*q+3],hv.w,a1);
      a2=fmaf(wreg[2][4*q+0],hv.x,a2); a2=fmaf(wreg[2][4*q+1],hv.y,a2);
      a2=fmaf(wreg[2][4*q+2],hv.z,a2); a2=fmaf(wreg[2][4*q+3],hv.w,a2);
      a3=fmaf(wreg[3][4*q+0],hv.x,a3); a3=fmaf(wreg[3][4*q+1],hv.y,a3);
      a3=fmaf(wreg[3][4*q+2],hv.z,a3); a3=fmaf(wreg[3][4*q+3],hv.w,a3);
    }
    // reduce across the 8 k-partitions (8 consecutive lanes)
    #pragma unroll
    for (int off=4; off>=1; off>>=1) {
      a0 += __shfl_xor_sync(0xffffffffu, a0, off);
      a1 += __shfl_xor_sync(0xffffffffu, a1, off);
      a2 += __shfl_xor_sync(0xffffffffu, a2, off);
      a3 += __shfl_xor_sync(0xffffffffu, a3, off);
    }
    if (kp == 0)
      *(float4*)&gates_s[4*rq] = make_float4(a0+xpv.x, a1+xpv.y, a2+xpv.z, a3+xpv.w);
    __syncthreads();

    if (tid < 32) {
      float gi = sigmoidf_(gates_s[tid]);
      float gf = sigmoidf_(gates_s[32+tid]);
      float gg = tanhf   (gates_s[64+tid]);
      float go = sigmoidf_(gates_s[96+tid]);
      float c  = gf*c_s[tid] + gi*gg;
      c_s[tid] = c;
      float h  = go * tanhf(c);
      int ug = 32*j + tid;
      uint32_t daddr = (cur ? hs0 : hs1) + ug*4u;   // next-step buffer
      #pragma unroll
      for (int p=0;p<8;p++) st_remote_f32(daddr, (uint32_t)p, h);
      h_out[(size_t)(t*BATCH+b)*HID + ug] = h;
    }
    cluster_sync_();  // release remote stores / acquire for next step
  }
}

// ============================================================
// gate[r] = sigmoid( tanh(h2_r @ gw1^T + gb1) @ gw2^T + gb2 )
// ============================================================
__global__ void __launch_bounds__(256) gate_kernel(
    const float* __restrict__ gw1, const float* __restrict__ gb1,
    const float* __restrict__ gw2, const float* __restrict__ gb2)
{
  __shared__ __align__(16) float Hs[8][256];
  __shared__ float wp_s[8][8];
  const int tid = threadIdx.x;
  const int r0  = blockIdx.x * 8;

  for (int idx = tid; idx < 8*256; idx += 256) {
    int row = idx >> 8, k = idx & 255;
    Hs[row][k] = g_h2[(size_t)(r0+row)*HID + k];
  }
  __syncthreads();

  float u[8];
  #pragma unroll
  for (int r=0;r<8;r++) u[r]=0.f;
  const float* wrow = gw1 + (size_t)tid*256;
  #pragma unroll 8
  for (int k0=0;k0<256;k0+=4){
    float4 w4 = *(const float4*)(wrow + k0);
    const float* wv = (const float*)&w4;
    #pragma unroll
    for (int kk=0;kk<4;kk++)
      #pragma unroll
      for (int r=0;r<8;r++) u[r] = fmaf(wv[kk], Hs[r][k0+kk], u[r]);
  }
  float g2 = gw2[tid], b1v = gb1[tid];
  float p[8];
  #pragma unroll
  for (int r=0;r<8;r++) p[r] = tanhf(u[r] + b1v) * g2;
  #pragma unroll
  for (int off=16; off>=1; off>>=1)
    #pragma unroll
    for (int r=0;r<8;r++) p[r] += __shfl_xor_sync(0xffffffffu, p[r], off);
  if ((tid & 31) == 0)
    #pragma unroll
    for (int r=0;r<8;r++) wp_s[tid>>5][r] = p[r];
  __syncthreads();
  if (tid < 8) {
    float s = 0.f;
    #pragma unroll
    for (int w=0;w<8;w++) s += wp_s[w][tid];     // fixed order: deterministic
    g_gate[r0 + tid] = sigmoidf_(s + gb2[0]);
  }
}

// ============================================================
// out[(b,t),v] = (h2_r * gate[r]) @ out_w^T + out_b
// fp32 128x128x16 double-buffered tile, 8x8 microtile, 256 threads
// ============================================================
__global__ void __launch_bounds__(256) out_gemm(
    const float* __restrict__ ow, const float* __restrict__ ob,
    float* __restrict__ outp)
{
  __shared__ __align__(16) float As[2][16][128];
  __shared__ __align__(16) float Bs[2][16][128];
  const int tid = threadIdx.x;
  const int bn  = blockIdx.x * 128;
  const int bm  = blockIdx.y * 128;
  const int lm  = tid >> 1;          // 0..127
  const int lq4 = (tid & 1) * 8;     // k offset within chunk: 0 or 8
  const int gm  = bm + lm;
  const bool mvalid = gm < NROWS;
  const float ga = mvalid ? g_gate[gm] : 0.f;
  const float* ap = g_h2 + (size_t)(mvalid ? gm : 0) * HID;
  const float* bp = ow   + (size_t)(bn + lm) * HID;
  const int tx = tid & 15, ty = tid >> 4;

  float acc[8][8];
  #pragma unroll
  for (int i=0;i<8;i++)
    #pragma unroll
    for (int jj=0;jj<8;jj++) acc[i][jj]=0.f;

  float4 ar0, ar1, br0, br1;
  ar0 = *(const float4*)(ap + lq4);
  ar1 = *(const float4*)(ap + lq4 + 4);
  br0 = *(const float4*)(bp + lq4);
  br1 = *(const float4*)(bp + lq4 + 4);

  int buf = 0;
  {
    const float *a0=(const float*)&ar0, *a1=(const float*)&ar1;
    const float *b0=(const float*)&br0, *b1=(const float*)&br1;
    #pragma unroll
    for (int kk=0;kk<4;kk++){
      As[buf][lq4+kk  ][lm] = a0[kk]*ga;
      As[buf][lq4+4+kk][lm] = a1[kk]*ga;
      Bs[buf][lq4+kk  ][lm] = b0[kk];
      Bs[buf][lq4+4+kk][lm] = b1[kk];
    }
  }
  __syncthreads();

  for (int kt = 0; kt < HID; kt += 16) {
    const bool more = (kt + 16) < HID;
    if (more) {
      ar0 = *(const float4*)(ap + kt+16 + lq4);
      ar1 = *(const float4*)(ap + kt+16 + lq4 + 4);
      br0 = *(const float4*)(bp + kt+16 + lq4);
      br1 = *(const float4*)(bp + kt+16 + lq4 + 4);
    }
    #pragma unroll 4
    for (int kk=0;kk<16;kk++){
      float4 av0 = *(const float4*)&As[buf][kk][ty*8];
      float4 av1 = *(const float4*)&As[buf][kk][ty*8+4];
      float4 bv0 = *(const float4*)&Bs[buf][kk][tx*8];
      float4 bv1 = *(const float4*)&Bs[buf][kk][tx*8+4];
      const float aa[8] = {av0.x,av0.y,av0.z,av0.w,av1.x,av1.y,av1.z,av1.w};
      const float bb[8] = {bv0.x,bv0.y,bv0.z,bv0.w,bv1.x,bv1.y,bv1.z,bv1.w};
      #pragma unroll
      for (int i=0;i<8;i++)
        #pragma unroll
        for (int jj=0;jj<8;jj++)
          acc[i][jj] = fmaf(aa[i], bb[jj], acc[i][jj]);
    }
    if (more) {
      buf ^= 1;
      const float *a0=(const float*)&ar0, *a1=(const float*)&ar1;
      const float *b0=(const float*)&br0, *b1=(const float*)&br1;
      #pragma unroll
      for (int kk=0;kk<4;kk++){
        As[buf][lq4+kk  ][lm] = a0[kk]*ga;
        As[buf][lq4+4+kk][lm] = a1[kk]*ga;
        Bs[buf][lq4+kk  ][lm] = b0[kk];
        Bs[buf][lq4+4+kk][lm] = b1[kk];
      }
      __syncthreads();
    }
  }

  float4 ob0 = *(const float4*)&ob[bn + tx*8];
  float4 ob1 = *(const float4*)&ob[bn + tx*8 + 4];
  #pragma unroll
  for (int i=0;i<8;i++){
    int m = bm + ty*8 + i;
    if (m < NROWS) {
      int bb = m & 7, tt = m >> 3;
      float* op = outp + (size_t)(bb*STEPS + tt)*VOCAB + bn + tx*8;
      float4 o0, o1;
      o0.x=acc[i][0]+ob0.x; o0.y=acc[i][1]+ob0.y; o0.z=acc[i][2]+ob0.z; o0.w=acc[i][3]+ob0.w;
      o1.x=acc[i][4]+ob1.x; o1.y=acc[i][5]+ob1.y; o1.z=acc[i][6]+ob1.z; o1.w=acc[i][7]+ob1.w;
      *(float4*)(op)   = o0;
      *(float4*)(op+4) = o1;
    }
  }
}

// ============================================================
extern "C" void kernel_launch(void* const* d_in, const int* in_sizes, int n_in,
                              void* d_out, int out_size) {
  const float* thought = (const float*)d_in[0];
  const int*   captions= (const int*)  d_in[1];
  const float* emb_w   = (const float*)d_in[2];
  const float* w_ih0   = (const float*)d_in[3];
  const float* w_hh0   = (const float*)d_in[4];
  const float* b_ih0   = (const float*)d_in[5];
  const float* b_hh0   = (const float*)d_in[6];
  const float* w_ih1   = (const float*)d_in[7];
  const float* w_hh1   = (const float*)d_in[8];
  const float* b_ih1   = (const float*)d_in[9];
  const float* b_hh1   = (const float*)d_in[10];
  const float* gw1     = (const float*)d_in[11];
  const float* gb1     = (const float*)d_in[12];
  const float* gw2     = (const float*)d_in[13];
  const float* gb2     = (const float*)d_in[14];
  const float* ow      = (const float*)d_in[15];
  const float* ob      = (const float*)d_in[16];
  float* outp = (float*)d_out;

  // layer 0: embed + input projection, then scan
  xp_kernel<<<STEPS, 256>>>(captions, emb_w, w_ih0, b_ih0, b_hh0, 128);
  lstm_scan<<<64, 256>>>(w_hh0, thought, 0);
  // layer 1: input projection from h1, then scan
  xp_kernel<<<STEPS, 256>>>(nullptr, nullptr, w_ih1, b_ih1, b_hh1, 256);
  lstm_scan<<<64, 256>>>(w_hh1, thought, 1);
  // gate MLP
  gate_kernel<<<STEPS, 256>>>(gw1, gb1, gw2, gb2);
  // final vocab projection
  dim3 gg(VOCAB/128, (NROWS+127)/128);
  out_gemm<<<gg, 256>>>(ow, ob, outp);
}

// round 4
// speedup vs baseline: 1.4132x; 1.4132x over previous
#include <cuda_runtime.h>
#include <cuda_bf16.h>
#include <cstdint>
#include <math.h>

#define STEPS 511
#define BATCH 8
#define HID   256
#define G4    1024
#define VOCAB 32000
#define NROWS (STEPS*BATCH)   // 4088
#define NPAD  4096
#define KCAT  768             // [hi | hi/lo split] concat K

// ---------------- scratch (no allocs allowed) ----------------
__device__ float g_xp[STEPS*BATCH*G4];
__device__ float g_h1[STEPS*BATCH*HID];
__device__ float g_h2[STEPS*BATCH*HID];
__device__ float g_gate[NROWS];
__device__ __nv_bfloat16 g_wcat[(size_t)VOCAB*KCAT];  // 49 MB
__device__ __nv_bfloat16 g_acat[(size_t)NPAD*KCAT];   // 6.3 MB

__device__ __forceinline__ float sigmoidf_(float x){ return 1.0f/(1.0f + __expf(-x)); }

__device__ __forceinline__ uint32_t smem_u32(const void* p){
  return (uint32_t)__cvta_generic_to_shared(p);
}
__device__ __forceinline__ void mbar_init_(uint32_t a, uint32_t cnt){
  asm volatile("mbarrier.init.shared.b64 [%0], %1;" :: "r"(a), "r"(cnt) : "memory");
}
__device__ __forceinline__ void mbar_expect_tx_(uint32_t a, uint32_t bytes){
  asm volatile("mbarrier.arrive.expect_tx.shared.b64 _, [%0], %1;" :: "r"(a), "r"(bytes) : "memory");
}
__device__ __forceinline__ void mbar_wait_(uint32_t a, uint32_t phase){
  asm volatile("{\n\t.reg .pred P;\n\t"
    "WL_%=:\n\t"
    "mbarrier.try_wait.parity.acquire.cta.shared::cta.b64 P, [%0], %1, 0x989680;\n\t"
    "@P bra.uni WD_%=;\n\t"
    "bra.uni WL_%=;\n\t"
    "WD_%=:\n\t}" :: "r"(a), "r"(phase) : "memory");
}
__device__ __forceinline__ void st_async_b32_(uint32_t saddr, uint32_t smbar, uint32_t rank, uint32_t v){
  asm volatile("{\n\t.reg .b32 ra, rb;\n\t"
    "mapa.shared::cluster.u32 ra, %0, %2;\n\t"
    "mapa.shared::cluster.u32 rb, %1, %2;\n\t"
    "st.async.shared::cluster.mbarrier::complete_tx::bytes.b32 [ra], %3, [rb];\n\t}"
    :: "r"(saddr), "r"(smbar), "r"(rank), "r"(v) : "memory");
}
__device__ __forceinline__ void cluster_sync_(){
  asm volatile("barrier.cluster.arrive.aligned;" ::: "memory");
  asm volatile("barrier.cluster.wait.aligned;"   ::: "memory");
}
__device__ __forceinline__ void cp_async16_(uint32_t saddr, const void* gaddr){
  asm volatile("cp.async.cg.shared.global [%0], [%1], 16;" :: "r"(saddr), "l"(gaddr) : "memory");
}
#define CP_COMMIT() asm volatile("cp.async.commit_group;" ::: "memory")
#define CP_WAIT1()  asm volatile("cp.async.wait_group 1;" ::: "memory")
#define CP_WAIT0()  asm volatile("cp.async.wait_group 0;" ::: "memory")

__device__ __forceinline__ void ldsm_x4_(uint32_t* r, uint32_t addr){
  asm volatile("ldmatrix.sync.aligned.m8n8.x4.shared.b16 {%0,%1,%2,%3}, [%4];"
    : "=r"(r[0]), "=r"(r[1]), "=r"(r[2]), "=r"(r[3]) : "r"(addr));
}
__device__ __forceinline__ void mma16816_(float* d, const uint32_t* a, const uint32_t* b){
  asm volatile("mma.sync.aligned.m16n8k16.row.col.f32.bf16.bf16.f32 "
    "{%0,%1,%2,%3}, {%4,%5,%6,%7}, {%8,%9}, {%0,%1,%2,%3};"
    : "+f"(d[0]), "+f"(d[1]), "+f"(d[2]), "+f"(d[3])
    : "r"(a[0]), "r"(a[1]), "r"(a[2]), "r"(a[3]), "r"(b[0]), "r"(b[1]));
}
static __device__ __forceinline__ uint32_t sw128_(uint32_t b){ return b ^ ((b >> 3) & 0x70u); }

// ============================================================
// Input projection
// ============================================================
__global__ void __launch_bounds__(256) xp_kernel(
    const int* __restrict__ captions, const float* __restrict__ emb_w,
    const float* __restrict__ W, const float* __restrict__ bias1,
    const float* __restrict__ bias2, int K)
{
  __shared__ __align__(16) float As[8][256];
  const int tid = threadIdx.x;
  const int r0  = blockIdx.x * 8;

  for (int idx = tid; idx < 8*K; idx += 256) {
    int row = idx / K, k = idx - row*K;
    int r = r0 + row;
    const float* src;
    if (captions) { int b = r & 7; int t = r >> 3; src = emb_w + (size_t)captions[b*512 + t] * K; }
    else          { src = g_h1 + (size_t)r * K; }
    As[row][k] = src[k];
  }
  __syncthreads();

  float acc[4][8];
  #pragma unroll
  for (int i=0;i<4;i++)
    #pragma unroll
    for (int r=0;r<8;r++) acc[i][r]=0.f;

  const int c0 = tid;
  for (int k0 = 0; k0 < K; k0 += 4) {
    float4 w0 = *(const float4*)&W[(size_t)(c0      )*K + k0];
    float4 w1 = *(const float4*)&W[(size_t)(c0+256)*K + k0];
    float4 w2 = *(const float4*)&W[(size_t)(c0+512)*K + k0];
    float4 w3 = *(const float4*)&W[(size_t)(c0+768)*K + k0];
    const float* v0 = (const float*)&w0;
    const float* v1 = (const float*)&w1;
    const float* v2 = (const float*)&w2;
    const float* v3 = (const float*)&w3;
    #pragma unroll
    for (int kk=0; kk<4; kk++) {
      #pragma unroll
      for (int r=0;r<8;r++) {
        float a = As[r][k0+kk];
        acc[0][r] = fmaf(v0[kk], a, acc[0][r]);
        acc[1][r] = fmaf(v1[kk], a, acc[1][r]);
        acc[2][r] = fmaf(v2[kk], a, acc[2][r]);
        acc[3][r] = fmaf(v3[kk], a, acc[3][r]);
      }
    }
  }
  #pragma unroll
  for (int i=0;i<4;i++) {
    int c = c0 + i*256;
    float bb = bias1[c] + bias2[c];
    #pragma unroll
    for (int r=0;r<8;r++)
      g_xp[(size_t)(r0+r)*G4 + c] = acc[i][r] + bb;
  }
}

// ============================================================
// LSTM scan with st.async + mbarrier tx sync
// ============================================================
__global__ __launch_bounds__(256,1) __cluster_dims__(8,1,1)
void lstm_scan(const float* __restrict__ w_hh,
               const float* __restrict__ thought,
               int layer)
{
  __shared__ __align__(16) float h_s[2][HID];
  __shared__ __align__(16) float gates_s[128];
  __shared__ float c_s[32];
  __shared__ __align__(8) unsigned long long mbar_sto[2];

  float* __restrict__ h_out = layer ? g_h2 : g_h1;

  const int tid = threadIdx.x;
  const int b   = blockIdx.x >> 3;
  const int j   = blockIdx.x & 7;
  const int rq  = tid >> 3;
  const int kp  = tid & 7;
  const int gidx = rq >> 3;
  const int ulb  = (4*rq) & 31;
  const int Gbase = gidx*256 + 32*j + ulb;

  float wreg[4][32];
  #pragma unroll
  for (int i=0;i<4;i++){
    const float* wp = w_hh + (size_t)(Gbase+i)*HID + 32*kp;
    #pragma unroll
    for (int q=0;q<8;q++){
      float4 v = *(const float4*)(wp + 4*q);
      wreg[i][4*q+0]=v.x; wreg[i][4*q+1]=v.y; wreg[i][4*q+2]=v.z; wreg[i][4*q+3]=v.w;
    }
  }

  const uint32_t mb0 = smem_u32(&mbar_sto[0]);
  const uint32_t mb1 = smem_u32(&mbar_sto[1]);
  if (tid == 0) {
    mbar_init_(mb0, 1); mbar_init_(mb1, 1);
    mbar_expect_tx_(mb0, 1024); mbar_expect_tx_(mb1, 1024);
  }
  h_s[0][tid] = thought[b*HID + tid];
  if (tid < 32) c_s[tid] = 0.f;
  __syncthreads();
  cluster_sync_();   // peers' mbarriers initialized before any st.async

  const uint32_t hs0 = smem_u32(&h_s[0][0]);
  const uint32_t hs1 = smem_u32(&h_s[1][0]);

  for (int t = 0; t < STEPS; t++) {
    const int cur = t & 1;
    if (t > 0) {
      mbar_wait_(cur ? mb1 : mb0, ((uint32_t)(t-1) >> 1) & 1u);
      if (tid == 0) mbar_expect_tx_(cur ? mb1 : mb0, 1024);  // re-arm next phase
    }

    float4 xpv = make_float4(0.f,0.f,0.f,0.f);
    if (kp == 0)
      xpv = *(const float4*)&g_xp[(size_t)(t*BATCH + b)*G4 + Gbase];

    float a0=0.f,a1=0.f,a2=0.f,a3=0.f;
    const float4* h4 = (const float4*)&h_s[cur][32*kp];
    #pragma unroll
    for (int q=0;q<8;q++) {
      float4 hv = h4[q];
      a0=fmaf(wreg[0][4*q+0],hv.x,a0); a0=fmaf(wreg[0][4*q+1],hv.y,a0);
      a0=fmaf(wreg[0][4*q+2],hv.z,a0); a0=fmaf(wreg[0][4*q+3],hv.w,a0);
      a1=fmaf(wreg[1][4*q+0],hv.x,a1); a1=fmaf(wreg[1][4*q+1],hv.y,a1);
      a1=fmaf(wreg[1][4*q+2],hv.z,a1); a1=fmaf(wreg[1][4*q+3],hv.w,a1);
      a2=fmaf(wreg[2][4*q+0],hv.x,a2); a2=fmaf(wreg[2][4*q+1],hv.y,a2);
      a2=fmaf(wreg[2][4*q+2],hv.z,a2); a2=fmaf(wreg[2][4*q+3],hv.w,a2);
      a3=fmaf(wreg[3][4*q+0],hv.x,a3); a3=fmaf(wreg[3][4*q+1],hv.y,a3);
      a3=fmaf(wreg[3][4*q+2],hv.z,a3); a3=fmaf(wreg[3][4*q+3],hv.w,a3);
    }
    #pragma unroll
    for (int off=4; off>=1; off>>=1) {
      a0 += __shfl_xor_sync(0xffffffffu, a0, off);
      a1 += __shfl_xor_sync(0xffffffffu, a1, off);
      a2 += __shfl_xor_sync(0xffffffffu, a2, off);
      a3 += __shfl_xor_sync(0xffffffffu, a3, off);
    }
    if (kp == 0)
      *(float4*)&gates_s[4*rq] = make_float4(a0+xpv.x, a1+xpv.y, a2+xpv.z, a3+xpv.w);
    __syncthreads();

    if (tid < 32) {
      float gi = sigmoidf_(gates_s[tid]);
      float gf = sigmoidf_(gates_s[32+tid]);
      float gg = 2.f*sigmoidf_(2.f*gates_s[64+tid]) - 1.f;   // tanh
      float go = sigmoidf_(gates_s[96+tid]);
      float c  = gf*c_s[tid] + gi*gg;
      c_s[tid] = c;
      float h  = go * (2.f*sigmoidf_(2.f*c) - 1.f);
      int ug = 32*j + tid;
      h_out[(size_t)(t*BATCH+b)*HID + ug] = h;
      if (t + 1 < STEPS) {
        uint32_t daddr = (cur ? hs0 : hs1) + (uint32_t)ug*4u;   // next-step buffer
        uint32_t dmb   = cur ? mb0 : mb1;
        uint32_t hv = __float_as_uint(h);
        #pragma unroll
        for (int p=0;p<8;p++) st_async_b32_(daddr, dmb, (uint32_t)p, hv);
      }
    }
  }
}

// ============================================================
// gate MLP
// ============================================================
__global__ void __launch_bounds__(256) gate_kernel(
    const float* __restrict__ gw1, const float* __restrict__ gb1,
    const float* __restrict__ gw2, const float* __restrict__ gb2)
{
  __shared__ __align__(16) float Hs[8][256];
  __shared__ float wp_s[8][8];
  const int tid = threadIdx.x;
  const int r0  = blockIdx.x * 8;

  for (int idx = tid; idx < 8*256; idx += 256) {
    int row = idx >> 8, k = idx & 255;
    Hs[row][k] = g_h2[(size_t)(r0+row)*HID + k];
  }
  __syncthreads();

  float u[8];
  #pragma unroll
  for (int r=0;r<8;r++) u[r]=0.f;
  const float* wrow = gw1 + (size_t)tid*256;
  #pragma unroll 8
  for (int k0=0;k0<256;k0+=4){
    float4 w4 = *(const float4*)(wrow + k0);
    const float* wv = (const float*)&w4;
    #pragma unroll
    for (int kk=0;kk<4;kk++)
      #pragma unroll
      for (int r=0;r<8;r++) u[r] = fmaf(wv[kk], Hs[r][k0+kk], u[r]);
  }
  float g2 = gw2[tid], b1v = gb1[tid];
  float p[8];
  #pragma unroll
  for (int r=0;r<8;r++) p[r] = tanhf(u[r] + b1v) * g2;
  #pragma unroll
  for (int off=16; off>=1; off>>=1)
    #pragma unroll
    for (int r=0;r<8;r++) p[r] += __shfl_xor_sync(0xffffffffu, p[r], off);
  if ((tid & 31) == 0)
    #pragma unroll
    for (int r=0;r<8;r++) wp_s[tid>>5][r] = p[r];
  __syncthreads();
  if (tid < 8) {
    float s = 0.f;
    #pragma unroll
    for (int w=0;w<8;w++) s += wp_s[w][tid];
    g_gate[r0 + tid] = sigmoidf_(s + gb2[0]);
  }
}

// ============================================================
// split-bf16 conversion:
//   W_cat[v] = [hi(w) | hi(w) | lo(w)]      (768)
//   A_cat[r] = [hi(a) | lo(a) | hi(a)]      a = h2*gate
// ============================================================
__global__ void __launch_bounds__(256) wcat_kernel(const float* __restrict__ ow){
  const int v = blockIdx.x, k = threadIdx.x;
  float w = ow[(size_t)v*HID + k];
  __nv_bfloat16 hi = __float2bfloat16(w);
  __nv_bfloat16 lo = __float2bfloat16(w - __bfloat162float(hi));
  __nv_bfloat16* row = g_wcat + (size_t)v*KCAT;
  row[k] = hi; row[HID + k] = hi; row[2*HID + k] = lo;
}

__global__ void __launch_bounds__(256) acat_kernel(){
  const int r = blockIdx.x, k = threadIdx.x;
  __nv_bfloat16* row = g_acat + (size_t)r*KCAT;
  if (r < NROWS) {
    float a = g_h2[(size_t)r*HID + k] * g_gate[r];
    __nv_bfloat16 hi = __float2bfloat16(a);
    __nv_bfloat16 lo = __float2bfloat16(a - __bfloat162float(hi));
    row[k] = hi; row[HID + k] = lo; row[2*HID + k] = hi;
  } else {
    __nv_bfloat16 z = __float2bfloat16(0.f);
    row[k] = z; row[HID + k] = z; row[2*HID + k] = z;
  }
}

// ============================================================
// out GEMM via mma.sync (bf16, fp32-accum), K=768 split-concat
// CTA tile 128(vocab) x 128(rows), 8 warps x (64x32), k-chunk 64,
// cp.async double buffer, smem-transpose epilogue (coalesced STG).
// ============================================================
#define KC 64
#define NCHUNK (KCAT/KC)             // 12
#define STAGE_HALF 16384             // 128 rows x 128 bytes
#define STAGE_SZ   32768             // W + A
#define EPS_STRIDE 132
#define GSMEM (2*STAGE_SZ + 4096)    // 68KB; epilogue (128*132*4=67584) overlays

__global__ void __launch_bounds__(256) out_gemm_mma(
    const float* __restrict__ ob, float* __restrict__ outp)
{
  extern __shared__ __align__(128) char smg[];
  const uint32_t sbase = smem_u32(smg);
  float* eps = (float*)smg;

  const int tid  = threadIdx.x;
  const int wid  = tid >> 5;
  const int lane = tid & 31;
  const int bn = blockIdx.x * 128;   // data-row tile
  const int bm = blockIdx.y * 128;   // vocab tile
  const int wm = (wid & 1) * 64;     // warp vocab offset
  const int wn = (wid >> 1) * 32;    // warp row offset

  // gmem/smem load mapping: 1024 16B segs per half; thread does 4 per half
  const int lrow = tid >> 1;            // 0..127
  const int lseg4 = (tid & 1) * 4;      // 4 segs of 16B

  // ---- prologue: chunks 0 and 1
  #pragma unroll
  for (int c = 0; c < 2; c++) {
    const uint32_t st = sbase + c*STAGE_SZ;
    const char* wg = (const char*)g_wcat + ((size_t)(bm+lrow)*KCAT + c*KC)*2;
    const char* ag = (const char*)g_acat + ((size_t)(bn+lrow)*KCAT + c*KC)*2;
    #pragma unroll
    for (int q=0;q<4;q++){
      uint32_t off = sw128_((uint32_t)(lrow*128 + (lseg4+q)*16));
      cp_async16_(st + off, wg + (lseg4+q)*16);
      cp_async16_(st + STAGE_HALF + off, ag + (lseg4+q)*16);
    }
    CP_COMMIT();
  }

  float acc[4][4][4];
  #pragma unroll
  for (int i=0;i<4;i++)
    #pragma unroll
    for (int jj=0;jj<4;jj++)
      #pragma unroll
      for (int v=0;v<4;v++) acc[i][jj][v]=0.f;

  // ldmatrix per-thread address components
  const uint32_t a_row = (uint32_t)(lane & 15);
  const uint32_t a_k16 = (uint32_t)((lane >> 4) * 16);
  const uint32_t b_row = (uint32_t)((lane & 7) + ((lane & 16) >> 1));
  const uint32_t b_k16 = (uint32_t)((lane & 8) ? 16 : 0);

  for (int c = 0; c < NCHUNK; c++) {
    CP_WAIT1();
    __syncthreads();
    const uint32_t wbase = sbase + (c & 1)*STAGE_SZ;
    const uint32_t abase = wbase + STAGE_HALF;

    #pragma unroll
    for (int k = 0; k < 4; k++) {
      uint32_t af[4][4], bf[2][4];
      #pragma unroll
      for (int mt=0; mt<4; mt++)
        ldsm_x4_(af[mt], wbase + sw128_((uint32_t)((wm + mt*16 + a_row)*128) + k*32 + a_k16));
      #pragma unroll
      for (int nt2=0; nt2<2; nt2++)
        ldsm_x4_(bf[nt2], abase + sw128_((uint32_t)((wn + nt2*16 + b_row)*128) + k*32 + b_k16));
      #pragma unroll
      for (int mt=0; mt<4; mt++)
        #pragma unroll
        for (int nt=0; nt<4; nt++)
          mma16816_(acc[mt][nt], af[mt], &bf[nt>>1][(nt&1)*2]);
    }
    __syncthreads();
    if (c + 2 < NCHUNK) {
      const uint32_t st = sbase + (c & 1)*STAGE_SZ;
      const char* wg = (const char*)g_wcat + ((size_t)(bm+lrow)*KCAT + (c+2)*KC)*2;
      const char* ag = (const char*)g_acat + ((size_t)(bn+lrow)*KCAT + (c+2)*KC)*2;
      #pragma unroll
      for (int q=0;q<4;q++){
        uint32_t off = sw128_((uint32_t)(lrow*128 + (lseg4+q)*16));
        cp_async16_(st + off, wg + (lseg4+q)*16);
        cp_async16_(st + STAGE_HALF + off, ag + (lseg4+q)*16);
      }
    }
    CP_COMMIT();   // keep group accounting uniform even when empty
  }
  CP_WAIT0();

  // ---- epilogue: transpose through smem -> coalesced float4 STG
  // acc val layout: v0:(m0,n0) v1:(m0,n0+1) v2:(m0+8,n0) v3:(m0+8,n0+1)
  {
    const int mq = lane >> 2;          // m offset
    const int nq = (lane & 3) * 2;     // n offset
    #pragma unroll
    for (int mt=0; mt<4; mt++)
      #pragma unroll
      for (int nt=0; nt<4; nt++){
        int m0 = wm + mt*16 + mq;
        int n0 = wn + nt*8 + nq;
        eps[(n0  )*EPS_STRIDE + m0    ] = acc[mt][nt][0];
        eps[(n0+1)*EPS_STRIDE + m0    ] = acc[mt][nt][1];
        eps[(n0  )*EPS_STRIDE + m0 + 8] = acc[mt][nt][2];
        eps[(n0+1)*EPS_STRIDE + m0 + 8] = acc[mt][nt][3];
      }
  }
  __syncthreads();

  {
    const int mo = (tid & 15) * 8;     // 8 floats per thread per row
    const int vg = bm + mo;
    float4 ob0 = *(const float4*)&ob[vg];
    float4 ob1 = *(const float4*)&ob[vg+4];
    #pragma unroll
    for (int it = 0; it < 8; it++) {
      int n = (tid >> 4) + it*16;
      int r = bn + n;
      if (r < NROWS) {
        const float* ep = eps + n*EPS_STRIDE + mo;
        float4 v0 = *(const float4*)ep;
        float4 v1 = *(const float4*)(ep+4);
        v0.x+=ob0.x; v0.y+=ob0.y; v0.z+=ob0.z; v0.w+=ob0.w;
        v1.x+=ob1.x; v1.y+=ob1.y; v1.z+=ob1.z; v1.w+=ob1.w;
        float* op = outp + (size_t)((r & 7)*STEPS + (r >> 3))*VOCAB + vg;
        *(float4*)op     = v0;
        *(float4*)(op+4) = v1;
      }
    }
  }
}

// ============================================================
extern "C" void kernel_launch(void* const* d_in, const int* in_sizes, int n_in,
                              void* d_out, int out_size) {
  const float* thought = (const float*)d_in[0];
  const int*   captions= (const int*)  d_in[1];
  const float* emb_w   = (const float*)d_in[2];
  const float* w_ih0   = (const float*)d_in[3];
  const float* w_hh0   = (const float*)d_in[4];
  const float* b_ih0   = (const float*)d_in[5];
  const float* b_hh0   = (const float*)d_in[6];
  const float* w_ih1   = (const float*)d_in[7];
  const float* w_hh1   = (const float*)d_in[8];
  const float* b_ih1   = (const float*)d_in[9];
  const float* b_hh1   = (const float*)d_in[10];
  const float* gw1     = (const float*)d_in[11];
  const float* gb1     = (const float*)d_in[12];
  const float* gw2     = (const float*)d_in[13];
  const float* gb2     = (const float*)d_in[14];
  const float* ow      = (const float*)d_in[15];
  const float* ob      = (const float*)d_in[16];
  float* outp = (float*)d_out;

  cudaFuncSetAttribute(out_gemm_mma, cudaFuncAttributeMaxDynamicSharedMemorySize, GSMEM);

  wcat_kernel<<<VOCAB, 256>>>(ow);
  xp_kernel<<<STEPS, 256>>>(captions, emb_w, w_ih0, b_ih0, b_hh0, 128);
  lstm_scan<<<64, 256>>>(w_hh0, thought, 0);
  xp_kernel<<<STEPS, 256>>>(nullptr, nullptr, w_ih1, b_ih1, b_hh1, 256);
  lstm_scan<<<64, 256>>>(w_hh1, thought, 1);
  gate_kernel<<<STEPS, 256>>>(gw1, gb1, gw2, gb2);
  acat_kernel<<<NPAD, 256>>>();
  dim3 gg(NPAD/128, VOCAB/128);   // (32, 250)
  out_gemm_mma<<<gg, 256, GSMEM>>>(ob, outp);
}

// round 5
// speedup vs baseline: 1.4826x; 1.0491x over previous
#include <cuda_runtime.h>
#include <cuda_bf16.h>
#include <cstdint>
#include <math.h>

#define STEPS 511
#define BATCH 8
#define HID   256
#define G4    1024
#define VOCAB 32000
#define NROWS (STEPS*BATCH)   // 4088
#define NPAD  4096
#define KCAT  768             // [hi | hi/lo split] concat K

// ---------------- scratch (no allocs allowed) ----------------
__device__ float g_xp[STEPS*BATCH*G4];                // gate-interleaved: [r][unit*4+gate]
__device__ float g_h1[STEPS*BATCH*HID];
__device__ float g_h2[STEPS*BATCH*HID];
__device__ float g_gate[NROWS];
__device__ __nv_bfloat16 g_wcat[(size_t)VOCAB*KCAT];  // 49 MB  out_w split
__device__ __nv_bfloat16 g_acat[(size_t)NPAD*KCAT];   // 6.3 MB (h1-split, then gated-h2-split)
__device__ __nv_bfloat16 g_xw[(size_t)G4*KCAT];       // 1.5 MB  w_ih1 split

__device__ __forceinline__ float sigmoidf_(float x){ return 1.0f/(1.0f + __expf(-x)); }

__device__ __forceinline__ uint32_t smem_u32(const void* p){
  return (uint32_t)__cvta_generic_to_shared(p);
}
__device__ __forceinline__ void mbar_init_(uint32_t a, uint32_t cnt){
  asm volatile("mbarrier.init.shared.b64 [%0], %1;" :: "r"(a), "r"(cnt) : "memory");
}
__device__ __forceinline__ void mbar_expect_tx_(uint32_t a, uint32_t bytes){
  asm volatile("mbarrier.arrive.expect_tx.shared.b64 _, [%0], %1;" :: "r"(a), "r"(bytes) : "memory");
}
__device__ __forceinline__ void mbar_wait_(uint32_t a, uint32_t phase){
  asm volatile("{\n\t.reg .pred P;\n\t"
    "WL_%=:\n\t"
    "mbarrier.try_wait.parity.acquire.cta.shared::cta.b64 P, [%0], %1, 0x989680;\n\t"
    "@P bra.uni WD_%=;\n\t"
    "bra.uni WL_%=;\n\t"
    "WD_%=:\n\t}" :: "r"(a), "r"(phase) : "memory");
}
__device__ __forceinline__ void st_async_b32_(uint32_t saddr, uint32_t smbar, uint32_t rank, uint32_t v){
  asm volatile("{\n\t.reg .b32 ra, rb;\n\t"
    "mapa.shared::cluster.u32 ra, %0, %2;\n\t"
    "mapa.shared::cluster.u32 rb, %1, %2;\n\t"
    "st.async.shared::cluster.mbarrier::complete_tx::bytes.b32 [ra], %3, [rb];\n\t}"
    :: "r"(saddr), "r"(smbar), "r"(rank), "r"(v) : "memory");
}
__device__ __forceinline__ void cluster_sync_(){
  asm volatile("barrier.cluster.arrive.aligned;" ::: "memory");
  asm volatile("barrier.cluster.wait.aligned;"   ::: "memory");
}
__device__ __forceinline__ void cp_async16_(uint32_t saddr, const void* gaddr){
  asm volatile("cp.async.cg.shared.global [%0], [%1], 16;" :: "r"(saddr), "l"(gaddr) : "memory");
}
#define CP_COMMIT() asm volatile("cp.async.commit_group;" ::: "memory")
#define CP_WAIT1()  asm volatile("cp.async.wait_group 1;" ::: "memory")
#define CP_WAIT0()  asm volatile("cp.async.wait_group 0;" ::: "memory")

__device__ __forceinline__ void ldsm_x4_(uint32_t* r, uint32_t addr){
  asm volatile("ldmatrix.sync.aligned.m8n8.x4.shared.b16 {%0,%1,%2,%3}, [%4];"
    : "=r"(r[0]), "=r"(r[1]), "=r"(r[2]), "=r"(r[3]) : "r"(addr));
}
__device__ __forceinline__ void mma16816_(float* d, const uint32_t* a, const uint32_t* b){
  asm volatile("mma.sync.aligned.m16n8k16.row.col.f32.bf16.bf16.f32 "
    "{%0,%1,%2,%3}, {%4,%5,%6,%7}, {%8,%9}, {%0,%1,%2,%3};"
    : "+f"(d[0]), "+f"(d[1]), "+f"(d[2]), "+f"(d[3])
    : "r"(a[0]), "r"(a[1]), "r"(a[2]), "r"(a[3]), "r"(b[0]), "r"(b[1]));
}
static __device__ __forceinline__ uint32_t sw128_(uint32_t b){ return b ^ ((b >> 3) & 0x70u); }

// ============================================================
// Layer-0 input projection (K=128), gate-interleaved output
// g_xp[r][unit*4+gate] = dot(emb_row(r), W[gate*256+unit]) + b1+b2
// ============================================================
__global__ void __launch_bounds__(256) xp0_kernel(
    const int* __restrict__ captions, const float* __restrict__ emb_w,
    const float* __restrict__ W, const float* __restrict__ bias1,
    const float* __restrict__ bias2)
{
  __shared__ __align__(16) float As[8][128];
  const int tid = threadIdx.x;
  const int r0  = blockIdx.x * 8;

  for (int idx = tid; idx < 8*128; idx += 256) {
    int row = idx >> 7, k = idx & 127;
    int r = r0 + row;
    int b = r & 7, t = r >> 3;
    As[row][k] = emb_w[(size_t)captions[b*512 + t] * 128 + k];
  }
  __syncthreads();

  float acc[4][8];
  #pragma unroll
  for (int i=0;i<4;i++)
    #pragma unroll
    for (int r=0;r<8;r++) acc[i][r]=0.f;

  const int c0 = tid;   // unit
  for (int k0 = 0; k0 < 128; k0 += 4) {
    float4 w0 = *(const float4*)&W[(size_t)(c0      )*128 + k0];
    float4 w1 = *(const float4*)&W[(size_t)(c0+256)*128 + k0];
    float4 w2 = *(const float4*)&W[(size_t)(c0+512)*128 + k0];
    float4 w3 = *(const float4*)&W[(size_t)(c0+768)*128 + k0];
    #pragma unroll
    for (int r=0;r<8;r++) {
      float4 a4 = *(const float4*)&As[r][k0];
      acc[0][r] = fmaf(w0.x, a4.x, acc[0][r]); acc[0][r] = fmaf(w0.y, a4.y, acc[0][r]);
      acc[0][r] = fmaf(w0.z, a4.z, acc[0][r]); acc[0][r] = fmaf(w0.w, a4.w, acc[0][r]);
      acc[1][r] = fmaf(w1.x, a4.x, acc[1][r]); acc[1][r] = fmaf(w1.y, a4.y, acc[1][r]);
      acc[1][r] = fmaf(w1.z, a4.z, acc[1][r]); acc[1][r] = fmaf(w1.w, a4.w, acc[1][r]);
      acc[2][r] = fmaf(w2.x, a4.x, acc[2][r]); acc[2][r] = fmaf(w2.y, a4.y, acc[2][r]);
      acc[2][r] = fmaf(w2.z, a4.z, acc[2][r]); acc[2][r] = fmaf(w2.w, a4.w, acc[2][r]);
      acc[3][r] = fmaf(w3.x, a4.x, acc[3][r]); acc[3][r] = fmaf(w3.y, a4.y, acc[3][r]);
      acc[3][r] = fmaf(w3.z, a4.z, acc[3][r]); acc[3][r] = fmaf(w3.w, a4.w, acc[3][r]);
    }
  }
  float bb[4];
  #pragma unroll
  for (int i=0;i<4;i++) bb[i] = bias1[c0+i*256] + bias2[c0+i*256];
  #pragma unroll
  for (int r=0;r<8;r++) {
    float4 o;
    o.x = acc[0][r]+bb[0]; o.y = acc[1][r]+bb[1];
    o.z = acc[2][r]+bb[2]; o.w = acc[3][r]+bb[3];
    *(float4*)&g_xp[(size_t)(r0+r)*G4 + c0*4] = o;
  }
}

// ============================================================
// LSTM scan: owner-direct units. thread=(u,kp), u=tid>>3, kp=tid&7.
// Thread owns all 4 gate rows of unit ug=32j+u; kp==0 lane does the
// activation fully in registers (c is a register). st.async h-exchange.
// ============================================================
__global__ __launch_bounds__(256,1) __cluster_dims__(8,1,1)
void lstm_scan2(const float* __restrict__ w_hh,
                const float* __restrict__ thought,
                int layer)
{
  __shared__ __align__(16) float h_s[2][HID];
  __shared__ __align__(8) unsigned long long mbar_sto[2];

  float* __restrict__ h_out = layer ? g_h2 : g_h1;

  const int tid = threadIdx.x;
  const int b   = blockIdx.x >> 3;
  const int j   = blockIdx.x & 7;
  const int u   = tid >> 3;       // unit within CTA slice (0..31)
  const int kp  = tid & 7;        // k partition
  const int ug  = 32*j + u;       // global unit

  // 4 gate rows (i,f,g,o) x 32-k slice in registers
  float wreg[4][32];
  #pragma unroll
  for (int g=0; g<4; g++){
    const float* wp = w_hh + (size_t)(g*256 + ug)*HID + 32*kp;
    #pragma unroll
    for (int q=0;q<8;q++){
      float4 v = *(const float4*)(wp + 4*q);
      wreg[g][4*q+0]=v.x; wreg[g][4*q+1]=v.y; wreg[g][4*q+2]=v.z; wreg[g][4*q+3]=v.w;
    }
  }

  const uint32_t mb0 = smem_u32(&mbar_sto[0]);
  const uint32_t mb1 = smem_u32(&mbar_sto[1]);
  if (tid == 0) {
    mbar_init_(mb0, 1); mbar_init_(mb1, 1);
    mbar_expect_tx_(mb0, 1024); mbar_expect_tx_(mb1, 1024);
  }
  h_s[0][tid] = thought[b*HID + tid];
  __syncthreads();
  cluster_sync_();   // peers' mbarriers initialized before any st.async

  const uint32_t hs0 = smem_u32(&h_s[0][0]);
  const uint32_t hs1 = smem_u32(&h_s[1][0]);
  const bool owner = (kp == 0);
  float c = 0.f;

  for (int t = 0; t < STEPS; t++) {
    const int cur = t & 1;
    if (t > 0) {
      mbar_wait_(cur ? mb1 : mb0, ((uint32_t)(t-1) >> 1) & 1u);
      if (tid == 0) mbar_expect_tx_(cur ? mb1 : mb0, 1024);  // re-arm next phase
    }

    float4 xpv = make_float4(0.f,0.f,0.f,0.f);
    if (owner)
      xpv = *(const float4*)&g_xp[(size_t)(t*BATCH + b)*G4 + ug*4];

    float a0=0.f,a1=0.f,a2=0.f,a3=0.f;
    const float4* h4 = (const float4*)&h_s[cur][32*kp];
    #pragma unroll
    for (int q=0;q<8;q++) {
      float4 hv = h4[q];
      a0=fmaf(wreg[0][4*q+0],hv.x,a0); a0=fmaf(wreg[0][4*q+1],hv.y,a0);
      a0=fmaf(wreg[0][4*q+2],hv.z,a0); a0=fmaf(wreg[0][4*q+3],hv.w,a0);
      a1=fmaf(wreg[1][4*q+0],hv.x,a1); a1=fmaf(wreg[1][4*q+1],hv.y,a1);
      a1=fmaf(wreg[1][4*q+2],hv.z,a1); a1=fmaf(wreg[1][4*q+3],hv.w,a1);
      a2=fmaf(wreg[2][4*q+0],hv.x,a2); a2=fmaf(wreg[2][4*q+1],hv.y,a2);
      a2=fmaf(wreg[2][4*q+2],hv.z,a2); a2=fmaf(wreg[2][4*q+3],hv.w,a2);
      a3=fmaf(wreg[3][4*q+0],hv.x,a3); a3=fmaf(wreg[3][4*q+1],hv.y,a3);
      a3=fmaf(wreg[3][4*q+2],hv.z,a3); a3=fmaf(wreg[3][4*q+3],hv.w,a3);
    }
    // reduce across 8 kp lanes (groups of 8 within the warp)
    #pragma unroll
    for (int off=4; off>=1; off>>=1) {
      a0 += __shfl_xor_sync(0xffffffffu, a0, off);
      a1 += __shfl_xor_sync(0xffffffffu, a1, off);
      a2 += __shfl_xor_sync(0xffffffffu, a2, off);
      a3 += __shfl_xor_sync(0xffffffffu, a3, off);
    }

    if (owner) {
      float gi = sigmoidf_(a0 + xpv.x);
      float gf = sigmoidf_(a1 + xpv.y);
      float gg = 2.f*sigmoidf_(2.f*(a2 + xpv.z)) - 1.f;   // tanh
      float go = sigmoidf_(a3 + xpv.w);
      c = gf*c + gi*gg;
      float h = go * (2.f*sigmoidf_(2.f*c) - 1.f);
      h_out[(size_t)(t*BATCH+b)*HID + ug] = h;
      if (t + 1 < STEPS) {
        uint32_t daddr = (cur ? hs0 : hs1) + (uint32_t)ug*4u;   // next-step buffer
        uint32_t dmb   = cur ? mb0 : mb1;
        uint32_t hv = __float_as_uint(h);
        #pragma unroll
        for (int p=0;p<8;p++) st_async_b32_(daddr, dmb, (uint32_t)p, hv);
      }
    }
  }
}

// ============================================================
// gate MLP
// ============================================================
__global__ void __launch_bounds__(256) gate_kernel(
    const float* __restrict__ gw1, const float* __restrict__ gb1,
    const float* __restrict__ gw2, const float* __restrict__ gb2)
{
  __shared__ __align__(16) float Hs[8][256];
  __shared__ float wp_s[8][8];
  const int tid = threadIdx.x;
  const int r0  = blockIdx.x * 8;

  for (int idx = tid; idx < 8*256; idx += 256) {
    int row = idx >> 8, k = idx & 255;
    Hs[row][k] = g_h2[(size_t)(r0+row)*HID + k];
  }
  __syncthreads();

  float u[8];
  #pragma unroll
  for (int r=0;r<8;r++) u[r]=0.f;
  const float* wrow = gw1 + (size_t)tid*256;
  #pragma unroll 8
  for (int k0=0;k0<256;k0+=4){
    float4 w4 = *(const float4*)(wrow + k0);
    #pragma unroll
    for (int r=0;r<8;r++) {
      float4 a4 = *(const float4*)&Hs[r][k0];
      u[r] = fmaf(w4.x, a4.x, u[r]); u[r] = fmaf(w4.y, a4.y, u[r]);
      u[r] = fmaf(w4.z, a4.z, u[r]); u[r] = fmaf(w4.w, a4.w, u[r]);
    }
  }
  float g2 = gw2[tid], b1v = gb1[tid];
  float p[8];
  #pragma unroll
  for (int r=0;r<8;r++) p[r] = tanhf(u[r] + b1v) * g2;
  #pragma unroll
  for (int off=16; off>=1; off>>=1)
    #pragma unroll
    for (int r=0;r<8;r++) p[r] += __shfl_xor_sync(0xffffffffu, p[r], off);
  if ((tid & 31) == 0)
    #pragma unroll
    for (int r=0;r<8;r++) wp_s[tid>>5][r] = p[r];
  __syncthreads();
  if (tid < 8) {
    float s = 0.f;
    #pragma unroll
    for (int w=0;w<8;w++) s += wp_s[w][tid];
    g_gate[r0 + tid] = sigmoidf_(s + gb2[0]);
  }
}

// ============================================================
// split-bf16 conversion kernels
// ============================================================
__global__ void __launch_bounds__(256) wcat_kernel(const float* __restrict__ ow){
  const int v = blockIdx.x, k = threadIdx.x;
  float w = ow[(size_t)v*HID + k];
  __nv_bfloat16 hi = __float2bfloat16(w);
  __nv_bfloat16 lo = __float2bfloat16(w - __bfloat162float(hi));
  __nv_bfloat16* row = g_wcat + (size_t)v*KCAT;
  row[k] = hi; row[HID + k] = hi; row[2*HID + k] = lo;
}

__global__ void __launch_bounds__(256) wihcvt_kernel(const float* __restrict__ wih){
  const int m = blockIdx.x, k = threadIdx.x;
  float w = wih[(size_t)m*HID + k];
  __nv_bfloat16 hi = __float2bfloat16(w);
  __nv_bfloat16 lo = __float2bfloat16(w - __bfloat162float(hi));
  __nv_bfloat16* row = g_xw + (size_t)m*KCAT;
  row[k] = hi; row[HID + k] = hi; row[2*HID + k] = lo;
}

__global__ void __launch_bounds__(256) h1cvt_kernel(){
  const int r = blockIdx.x, k = threadIdx.x;
  __nv_bfloat16* row = g_acat + (size_t)r*KCAT;
  if (r < NROWS) {
    float a = g_h1[(size_t)r*HID + k];
    __nv_bfloat16 hi = __float2bfloat16(a);
    __nv_bfloat16 lo = __float2bfloat16(a - __bfloat162float(hi));
    row[k] = hi; row[HID + k] = lo; row[2*HID + k] = hi;
  } else {
    __nv_bfloat16 z = __float2bfloat16(0.f);
    row[k] = z; row[HID + k] = z; row[2*HID + k] = z;
  }
}

__global__ void __launch_bounds__(256) acat_kernel(){
  const int r = blockIdx.x, k = threadIdx.x;
  __nv_bfloat16* row = g_acat + (size_t)r*KCAT;
  if (r < NROWS) {
    float a = g_h2[(size_t)r*HID + k] * g_gate[r];
    __nv_bfloat16 hi = __float2bfloat16(a);
    __nv_bfloat16 lo = __float2bfloat16(a - __bfloat162float(hi));
    row[k] = hi; row[HID + k] = lo; row[2*HID + k] = hi;
  } else {
    __nv_bfloat16 z = __float2bfloat16(0.f);
    row[k] = z; row[HID + k] = z; row[2*HID + k] = z;
  }
}

// ============================================================
// shared mma mainloop pieces
// ============================================================
#define KC 64
#define NCHUNK (KCAT/KC)             // 12
#define STAGE_HALF 16384             // 128 rows x 128 bytes
#define STAGE_SZ   32768             // W + A
#define EPS_STRIDE 132
#define GSMEM (2*STAGE_SZ + 4096)

// mainloop macro body shared by the two mma kernels (A=ws rows bm.., B=as rows bn..)
#define MMA_MAINLOOP(WSRC, ASRC)                                                  \
  const int lrow = tid >> 1;                                                      \
  const int lseg4 = (tid & 1) * 4;                                                \
  _Pragma("unroll")                                                               \
  for (int c = 0; c < 2; c++) {                                                   \
    const uint32_t st = sbase + c*STAGE_SZ;                                       \
    const char* wg = (const char*)(WSRC) + ((size_t)(bm+lrow)*KCAT + c*KC)*2;     \
    const char* ag = (const char*)(ASRC) + ((size_t)(bn+lrow)*KCAT + c*KC)*2;     \
    _Pragma("unroll")                                                             \
    for (int q=0;q<4;q++){                                                        \
      uint32_t off = sw128_((uint32_t)(lrow*128 + (lseg4+q)*16));                 \
      cp_async16_(st + off, wg + (lseg4+q)*16);                                   \
      cp_async16_(st + STAGE_HALF + off, ag + (lseg4+q)*16);                      \
    }                                                                             \
    CP_COMMIT();                                                                  \
  }                                                                               \
  float acc[4][4][4];                                                             \
  _Pragma("unroll")                                                               \
  for (int i=0;i<4;i++)                                                           \
    _Pragma("unroll")                                                             \
    for (int jj=0;jj<4;jj++)                                                      \
      _Pragma("unroll")                                                           \
      for (int v=0;v<4;v++) acc[i][jj][v]=0.f;                                    \
  const uint32_t a_row = (uint32_t)(lane & 15);                                   \
  const uint32_t a_k16 = (uint32_t)((lane >> 4) * 16);                            \
  const uint32_t b_row = (uint32_t)((lane & 7) + ((lane & 16) >> 1));             \
  const uint32_t b_k16 = (uint32_t)((lane & 8) ? 16 : 0);                         \
  for (int c = 0; c < NCHUNK; c++) {                                              \
    CP_WAIT1();                                                                   \
    __syncthreads();                                                              \
    const uint32_t wbase = sbase + (c & 1)*STAGE_SZ;                              \
    const uint32_t abase = wbase + STAGE_HALF;                                    \
    _Pragma("unroll")                                                             \
    for (int k = 0; k < 4; k++) {                                                 \
      uint32_t af[4][4], bf[2][4];                                                \
      _Pragma("unroll")                                                           \
      for (int mt=0; mt<4; mt++)                                                  \
        ldsm_x4_(af[mt], wbase + sw128_((uint32_t)((wm + mt*16 + a_row)*128) + k*32 + a_k16)); \
      _Pragma("unroll")                                                           \
      for (int nt2=0; nt2<2; nt2++)                                               \
        ldsm_x4_(bf[nt2], abase + sw128_((uint32_t)((wn + nt2*16 + b_row)*128) + k*32 + b_k16)); \
      _Pragma("unroll")                                                           \
      for (int mt=0; mt<4; mt++)                                                  \
        _Pragma("unroll")                                                         \
        for (int nt=0; nt<4; nt++)                                                \
          mma16816_(acc[mt][nt], af[mt], &bf[nt>>1][(nt&1)*2]);                   \
    }                                                                             \
    __syncthreads();                                                              \
    if (c + 2 < NCHUNK) {                                                         \
      const uint32_t st = sbase + (c & 1)*STAGE_SZ;                               \
      const char* wg = (const char*)(WSRC) + ((size_t)(bm+lrow)*KCAT + (c+2)*KC)*2; \
      const char* ag = (const char*)(ASRC) + ((size_t)(bn+lrow)*KCAT + (c+2)*KC)*2; \
      _Pragma("unroll")                                                           \
      for (int q=0;q<4;q++){                                                      \
        uint32_t off = sw128_((uint32_t)(lrow*128 + (lseg4+q)*16));               \
        cp_async16_(st + off, wg + (lseg4+q)*16);                                 \
        cp_async16_(st + STAGE_HALF + off, ag + (lseg4+q)*16);                    \
      }                                                                           \
    }                                                                             \
    CP_COMMIT();                                                                  \
  }                                                                               \
  CP_WAIT0();                                                                     \
  {                                                                               \
    const int mq = lane >> 2;                                                     \
    const int nq = (lane & 3) * 2;                                                \
    _Pragma("unroll")                                                             \
    for (int mt=0; mt<4; mt++)                                                    \
      _Pragma("unroll")                                                           \
      for (int nt=0; nt<4; nt++){                                                 \
        int m0 = wm + mt*16 + mq;                                                 \
        int n0 = wn + nt*8 + nq;                                                  \
        eps[(n0  )*EPS_STRIDE + m0    ] = acc[mt][nt][0];                         \
        eps[(n0+1)*EPS_STRIDE + m0    ] = acc[mt][nt][1];                         \
        eps[(n0  )*EPS_STRIDE + m0 + 8] = acc[mt][nt][2];                         \
        eps[(n0+1)*EPS_STRIDE + m0 + 8] = acc[mt][nt][3];                         \
      }                                                                           \
  }                                                                               \
  __syncthreads();

// ============================================================
// vocab GEMM (unchanged epilogue target)
// ============================================================
__global__ void __launch_bounds__(256) out_gemm_mma(
    const float* __restrict__ ob, float* __restrict__ outp)
{
  extern __shared__ __align__(128) char smg[];
  const uint32_t sbase = smem_u32(smg);
  float* eps = (float*)smg;
  const int tid  = threadIdx.x;
  const int wid  = tid >> 5;
  const int lane = tid & 31;
  const int bn = blockIdx.x * 128;
  const int bm = blockIdx.y * 128;
  const int wm = (wid & 1) * 64;
  const int wn = (wid >> 1) * 32;

  MMA_MAINLOOP(g_wcat, g_acat)

  {
    const int mo = (tid & 15) * 8;
    const int vg = bm + mo;
    float4 ob0 = *(const float4*)&ob[vg];
    float4 ob1 = *(const float4*)&ob[vg+4];
    #pragma unroll
    for (int it = 0; it < 8; it++) {
      int n = (tid >> 4) + it*16;
      int r = bn + n;
      if (r < NROWS) {
        const float* ep = eps + n*EPS_STRIDE + mo;
        float4 v0 = *(const float4*)ep;
        float4 v1 = *(const float4*)(ep+4);
        v0.x+=ob0.x; v0.y+=ob0.y; v0.z+=ob0.z; v0.w+=ob0.w;
        v1.x+=ob1.x; v1.y+=ob1.y; v1.z+=ob1.z; v1.w+=ob1.w;
        float* op = outp + (size_t)((r & 7)*STEPS + (r >> 3))*VOCAB + vg;
        *(float4*)op     = v0;
        *(float4*)(op+4) = v1;
      }
    }
  }
}

// ============================================================
// xp1 GEMM: g_xp[r][unit*4+gate] = g_xw(bm..) x g_acat(h1-split) + biases
// ============================================================
__global__ void __launch_bounds__(256) xp_gemm_mma(
    const float* __restrict__ bih, const float* __restrict__ bhh)
{
  extern __shared__ __align__(128) char smg[];
  const uint32_t sbase = smem_u32(smg);
  float* eps = (float*)smg;
  const int tid  = threadIdx.x;
  const int wid  = tid >> 5;
  const int lane = tid & 31;
  const int bn = blockIdx.x * 128;   // data rows
  const int bm = blockIdx.y * 128;   // gate rows (0..1023)
  const int wm = (wid & 1) * 64;
  const int wn = (wid >> 1) * 32;

  MMA_MAINLOOP(g_xw, g_acat)

  {
    const int mo = (tid & 15) * 8;
    const int mg = bm + mo;                       // gate-row base (8 consecutive)
    const int gate = bm >> 8;                     // constant within 128-tile
    const int ub = mg & 255;                      // unit base
    float bb[8];
    #pragma unroll
    for (int q=0;q<8;q++) bb[q] = bih[mg+q] + bhh[mg+q];
    #pragma unroll
    for (int it = 0; it < 8; it++) {
      int n = (tid >> 4) + it*16;
      int r = bn + n;
      if (r < NROWS) {
        const float* ep = eps + n*EPS_STRIDE + mo;
        float* op = g_xp + (size_t)r*G4 + ub*4 + gate;
        #pragma unroll
        for (int q=0;q<8;q++)
          op[q*4] = ep[q] + bb[q];
      }
    }
  }
}

// ============================================================
extern "C" void kernel_launch(void* const* d_in, const int* in_sizes, int n_in,
                              void* d_out, int out_size) {
  const float* thought = (const float*)d_in[0];
  const int*   captions= (const int*)  d_in[1];
  const float* emb_w   = (const float*)d_in[2];
  const float* w_ih0   = (const float*)d_in[3];
  const float* w_hh0   = (const float*)d_in[4];
  const float* b_ih0   = (const float*)d_in[5];
  const float* b_hh0   = (const float*)d_in[6];
  const float* w_ih1   = (const float*)d_in[7];
  const float* w_hh1   = (const float*)d_in[8];
  const float* b_ih1   = (const float*)d_in[9];
  const float* b_hh1   = (const float*)d_in[10];
  const float* gw1     = (const float*)d_in[11];
  const float* gb1     = (const float*)d_in[12];
  const float* gw2     = (const float*)d_in[13];
  const float* gb2     = (const float*)d_in[14];
  const float* ow      = (const float*)d_in[15];
  const float* ob      = (const float*)d_in[16];
  float* outp = (float*)d_out;

  cudaFuncSetAttribute(out_gemm_mma, cudaFuncAttributeMaxDynamicSharedMemorySize, GSMEM);
  cudaFuncSetAttribute(xp_gemm_mma,  cudaFuncAttributeMaxDynamicSharedMemorySize, GSMEM);

  wihcvt_kernel<<<G4, 256>>>(w_ih1);              // independent of scans
  wcat_kernel<<<VOCAB, 256>>>(ow);                // independent of scans
  xp0_kernel<<<STEPS, 256>>>(captions, emb_w, w_ih0, b_ih0, b_hh0);
  lstm_scan2<<<64, 256>>>(w_hh0, thought, 0);
  h1cvt_kernel<<<NPAD, 256>>>();
  {
    dim3 gx(NPAD/128, G4/128);                    // (32, 8)
    xp_gemm_mma<<<gx, 256, GSMEM>>>(b_ih1, b_hh1);
  }
  lstm_scan2<<<64, 256>>>(w_hh1, thought, 1);
  gate_kernel<<<STEPS, 256>>>(gw1, gb1, gw2, gb2);
  acat_kernel<<<NPAD, 256>>>();
  dim3 gg(NPAD/128, VOCAB/128);                   // (32, 250)
  out_gemm_mma<<<gg, 256, GSMEM>>>(ob, outp);
}